// round 9
// baseline (speedup 1.0000x reference)
#include <cuda_runtime.h>

// SSIM over (32,3,512,512) fp32 pairs, 7x7 box window, interior crop, scalar mean.
// Separable box filter, all-scalar fp32, block-wide staging (no halo).
// PAIR-SUM HORIZONTAL DECOMPOSITION: the staging thread computes its own pair's
// field sums once (SA,SB,SQ,SP; 8 flops) and stores them alongside the raw pair.
// A reader builds both its columns from 3 pair-sums (one kept in registers) plus
// 2 boundary singles:
//   col0 = odd(p[t-2]) + S(t-1)+S(t)+S(t+1)
//   col1 = S(t-1)+S(t)+S(t+1) + even(p[t+2])
// -> horizontal flops 43->30 per 2px/row, LDS 5->4. Vertical 7-row sliding sums
// via register rings (compile-time slots, period 7). 2 rows per __syncthreads
// with a 4-row double-buffer. Epilogue with 1/49 folded into constants and one
// shared reciprocal for both columns. NSTRIP=3 -> 288 CTAs = one full wave.
// Final reduction fused via last-block-done (fixed-order double sum).

#define W 512
#define H 512
#define NIMG 96            // 32 batch * 3 channels
#define NSTRIP 3
#define ROWS_OUT 169       // 3*169 = 507 >= 506 interior rows
#define NBLK (NIMG * NSTRIP)
#define NT 256             // thread t owns cols 2t, 2t+1

__device__ float g_part[NBLK];
__device__ unsigned int g_count;   // zero-init; reset by last block each launch

__device__ __forceinline__ float frcp(float x) {
    float r; asm("rcp.approx.f32 %0, %1;" : "=f"(r) : "f"(x)); return r;
}

// Process one staged row. BUFI: buffer index; J: ring slot (compile-time);
// KK: row-in-strip (emit masked to [6, klim]); oSA..oSP: this thread's own
// pair-sums for that row (kept in registers, not reloaded).
#define PROC_ROW(BUFI, J, KK, oSA, oSB, oSQ, oSP)                             \
do {                                                                          \
    const float4 r0 = s_raw[BUFI][p0];   /* need .z=ao .w=bo */               \
    const float4 m1 = s_sum[BUFI][p1];                                        \
    const float4 m3 = s_sum[BUFI][p3];                                        \
    const float4 r4 = s_raw[BUFI][p4];   /* need .x=ae .y=be */               \
    const float TA = (m1.x + oSA) + m3.x;                                     \
    const float TB = (m1.y + oSB) + m3.y;                                     \
    const float TQ = (m1.z + oSQ) + m3.z;                                     \
    const float TP = (m1.w + oSP) + m3.w;                                     \
    const float A0 = TA + r0.z;                                               \
    const float A1 = TA + r4.x;                                               \
    const float B0 = TB + r0.w;                                               \
    const float B1 = TB + r4.y;                                               \
    const float qo0 = fmaf(r0.w, r0.w, r0.z * r0.z);                          \
    const float qe4 = fmaf(r4.y, r4.y, r4.x * r4.x);                          \
    const float Q0 = TQ + qo0;                                                \
    const float Q1 = TQ + qe4;                                                \
    const float P0 = TP + r0.z * r0.w;                                        \
    const float P1 = TP + r4.x * r4.y;                                        \
    vA0 += A0 - rA0[J];  rA0[J] = A0;                                         \
    vB0 += B0 - rB0[J];  rB0[J] = B0;                                         \
    vQ0 += Q0 - rQ0[J];  rQ0[J] = Q0;                                         \
    vP0 += P0 - rP0[J];  rP0[J] = P0;                                         \
    vA1 += A1 - rA1[J];  rA1[J] = A1;                                         \
    vB1 += B1 - rB1[J];  rB1[J] = B1;                                         \
    vQ1 += Q1 - rQ1[J];  rQ1[J] = Q1;                                         \
    vP1 += P1 - rP1[J];  rP1[J] = P1;                                         \
    {                                                                         \
        const bool yok = ((KK) >= 6) && ((KK) <= klim);                       \
        /* col 0: raw window sums, 1/49 folded into constants */              \
        const float tt0 = vA0 * vB0;                                          \
        const float q20 = fmaf(vB0, vB0, vA0 * vA0);                          \
        const float A1v0 = fmaf(tt0, K_A1, C1);                               \
        float A2v0 = fmaf(vP0, K_P, C2);                                      \
        A2v0 = fmaf(tt0, K_A2, A2v0);                                         \
        const float B1v0 = fmaf(q20, K_B1, C1);                               \
        float B2v0 = fmaf(vQ0, K_Q, C2);                                      \
        B2v0 = fmaf(q20, K_B2, B2v0);                                         \
        const float N0 = A1v0 * A2v0;                                         \
        const float D0 = B1v0 * B2v0;                                         \
        /* col 1 */                                                           \
        const float tt1 = vA1 * vB1;                                          \
        const float q21 = fmaf(vB1, vB1, vA1 * vA1);                          \
        const float A1v1 = fmaf(tt1, K_A1, C1);                               \
        float A2v1 = fmaf(vP1, K_P, C2);                                      \
        A2v1 = fmaf(tt1, K_A2, A2v1);                                         \
        const float B1v1 = fmaf(q21, K_B1, C1);                               \
        float B2v1 = fmaf(vQ1, K_Q, C2);                                      \
        B2v1 = fmaf(q21, K_B2, B2v1);                                         \
        const float N1 = A1v1 * A2v1;                                         \
        const float D1 = B1v1 * B2v1;                                         \
        const float R = frcp(D0 * D1);                                        \
        const float S0 = N0 * D1 * R;                                         \
        const float S1 = N1 * D0 * R;                                         \
        acc += (ok0 && yok) ? S0 : 0.0f;                                      \
        acc += (ok1 && yok) ? S1 : 0.0f;                                      \
    }                                                                         \
} while (0)

__global__ void __launch_bounds__(NT, 2) ssim_main(const float* __restrict__ A,
                                                   const float* __restrict__ B,
                                                   float* __restrict__ out) {
    // NP=49, CONV_NORM=49/48, C1=1e-4, C2=9e-4; 1/49 folded:
    // ux = vA/49 etc. ->  ux*uy = tt/2401, ux^2+uy^2 = q2/2401
    const float C1   = 1e-4f;
    const float C2   = 9e-4f;
    const float K_A1 =  2.0f / 2401.0f;      // A1 = 2*ux*uy + C1
    const float K_A2 = -1.0f / 1176.0f;      // -2*CN/2401 = -(49/24)/2401
    const float K_P  =  1.0f / 24.0f;        // 2*CN/49
    const float K_B1 =  1.0f / 2401.0f;      // B1 = ux^2+uy^2 + C1
    const float K_Q  =  1.0f / 48.0f;        // CN/49
    const float K_B2 = -1.0f / 2352.0f;      // -CN/2401 = -(49/48)/2401

    const int t     = threadIdx.x;
    const int blk   = blockIdx.x;
    const int img   = blk % NIMG;
    const int strip = blk / NIMG;

    const size_t base = (size_t)img * (W * H);
    const float2* __restrict__ ap = (const float2*)(A + base) + t;
    const float2* __restrict__ bp = (const float2*)(B + base) + t;

    __shared__ float4 s_raw[4][NT];   // (ae, be, ao, bo)
    __shared__ float4 s_sum[4][NT];   // (SA, SB, SQ, SP) pair-sums

    // Loop-invariant pair indices (clamped entries feed only masked columns)
    const int p0 = max(t - 2, 0);
    const int p1 = max(t - 1, 0);
    const int p3 = min(t + 1, NT - 1);
    const int p4 = min(t + 2, NT - 1);

    const bool ok0 = (t >= 2) && (t <= 254);   // col 2t   in [3,508]
    const bool ok1 = (t >= 1) && (t <= 253);   // col 2t+1 in [3,508]

    const int rstart = strip * ROWS_OUT;       // 0 / 169 / 338
    // Last emitting k: strips 0,1 -> 174 (169 rows each); strip 2 -> 173 (168).
    const int klim = (strip == 2) ? 173 : 174;

    // Vertical sliding state (per column): A, B, Q(=Saa+Sbb), P(=Sab)
    float vA0 = 0.f, vB0 = 0.f, vQ0 = 0.f, vP0 = 0.f;
    float vA1 = 0.f, vB1 = 0.f, vQ1 = 0.f, vP1 = 0.f;
    float rA0[7] = {0,0,0,0,0,0,0}, rB0[7] = {0,0,0,0,0,0,0};
    float rQ0[7] = {0,0,0,0,0,0,0}, rP0[7] = {0,0,0,0,0,0,0};
    float rA1[7] = {0,0,0,0,0,0,0}, rB1[7] = {0,0,0,0,0,0,0};
    float rQ1[7] = {0,0,0,0,0,0,0}, rP1[7] = {0,0,0,0,0,0,0};
    float acc = 0.0f;

    // Prefetch rows 0,1
    float2 ra0 = __ldg(ap + (rstart + 0) * (W / 2));
    float2 rb0 = __ldg(bp + (rstart + 0) * (W / 2));
    float2 ra1 = __ldg(ap + (rstart + 1) * (W / 2));
    float2 rb1 = __ldg(bp + (rstart + 1) * (W / 2));

    int bufp = 0;   // buffer pair base: 0 or 2

    // 182 rows = 13 x (7 pairs). Ring slot = row%7 compile-time (14%7==0).
    // Rows 175..181 are clamped re-reads; emits beyond klim are masked.
    #pragma unroll 1
    for (int it = 0; it < 13; it++) {
        const int kb = it * 14;
        #pragma unroll
        for (int m = 0; m < 7; m++) {
            const int k0 = kb + 2 * m;

            // Build own pair-sums for both rows (kept in registers for PROC)
            const float SA0r = ra0.x + ra0.y;
            const float SB0r = rb0.x + rb0.y;
            float SQ0r = ra0.x * ra0.x;
            SQ0r = fmaf(rb0.x, rb0.x, SQ0r);
            SQ0r = fmaf(ra0.y, ra0.y, SQ0r);
            SQ0r = fmaf(rb0.y, rb0.y, SQ0r);
            const float SP0r = fmaf(ra0.y, rb0.y, ra0.x * rb0.x);

            const float SA1r = ra1.x + ra1.y;
            const float SB1r = rb1.x + rb1.y;
            float SQ1r = ra1.x * ra1.x;
            SQ1r = fmaf(rb1.x, rb1.x, SQ1r);
            SQ1r = fmaf(ra1.y, ra1.y, SQ1r);
            SQ1r = fmaf(rb1.y, rb1.y, SQ1r);
            const float SP1r = fmaf(ra1.y, rb1.y, ra1.x * rb1.x);

            s_raw[bufp    ][t] = make_float4(ra0.x, rb0.x, ra0.y, rb0.y);
            s_sum[bufp    ][t] = make_float4(SA0r, SB0r, SQ0r, SP0r);
            s_raw[bufp + 1][t] = make_float4(ra1.x, rb1.x, ra1.y, rb1.y);
            s_sum[bufp + 1][t] = make_float4(SA1r, SB1r, SQ1r, SP1r);

            // Prefetch next two rows (row-clamped; feeds only masked emits)
            const int rn0 = min(rstart + k0 + 2, H - 1) * (W / 2);
            const int rn1 = min(rstart + k0 + 3, H - 1) * (W / 2);
            ra0 = __ldg(ap + rn0);
            rb0 = __ldg(bp + rn0);
            ra1 = __ldg(ap + rn1);
            rb1 = __ldg(bp + rn1);

            __syncthreads();                 // one barrier per TWO rows

            PROC_ROW(bufp,     (2 * m) % 7,     k0,     SA0r, SB0r, SQ0r, SP0r);
            PROC_ROW(bufp + 1, (2 * m + 1) % 7, k0 + 1, SA1r, SB1r, SQ1r, SP1r);

            bufp ^= 2;
        }
    }

    // Deterministic block reduction
    #pragma unroll
    for (int o = 16; o > 0; o >>= 1)
        acc += __shfl_xor_sync(0xFFFFFFFFu, acc, o);

    __shared__ float wsum[8];
    __shared__ bool  is_last;
    if ((t & 31) == 0) wsum[t >> 5] = acc;
    __syncthreads();
    if (t == 0) {
        float v = wsum[0] + wsum[1] + wsum[2] + wsum[3]
                + wsum[4] + wsum[5] + wsum[6] + wsum[7];
        g_part[blk] = v;
        __threadfence();
        unsigned int prev = atomicAdd(&g_count, 1u);
        is_last = (prev == NBLK - 1);
    }
    __syncthreads();

    // Last finished CTA: fixed-order double-precision final sum (deterministic)
    if (is_last) {
        double s = 0.0;
        for (int i = t; i < NBLK; i += NT) s += (double)__ldcg(&g_part[i]);
        __shared__ double sd[NT];
        sd[t] = s;
        __syncthreads();
        #pragma unroll
        for (int st = NT / 2; st > 0; st >>= 1) {
            if (t < st) sd[t] += sd[t + st];
            __syncthreads();
        }
        if (t == 0) {
            out[0] = (float)(sd[0] * (1.0 / ((double)NIMG * 506.0 * 506.0)));
            g_count = 0;   // reset for next graph replay
        }
    }
}

extern "C" void kernel_launch(void* const* d_in, const int* in_sizes, int n_in,
                              void* d_out, int out_size) {
    const float* img1 = (const float*)d_in[0];
    const float* img2 = (const float*)d_in[1];
    float* out = (float*)d_out;
    (void)in_sizes; (void)n_in; (void)out_size;

    ssim_main<<<NBLK, NT>>>(img1, img2, out);
}

// round 10
// speedup vs baseline: 1.1365x; 1.1365x over previous
#include <cuda_runtime.h>
#include <cstdint>

// SSIM over (32,3,512,512) fp32 pairs, 7x7 box window, interior crop, scalar mean.
// Separable box filter, all-scalar fp32. cp.async (LDGSTS) GMEM->SMEM pipeline,
// depth 3 row-pairs: zero pre-barrier dependent work, 2-interval prefetch
// distance. Plane-split staging (threads 0-127 copy A rows, 128-255 copy B rows,
// one 16B cp.async per row each) into separate sA/sB rings. Readers own column
// pairs c0 = 4q+2h with warp-uniform parity h=t>>7; taps from 3 conflict-free
// LDS.128 per image. Horizontal col1 slid from col0; fields A,B,Q(=Saa+Sbb),
// P(=Sab); vertical 7-row sliding via register rings (compile-time slots).
// NSTRIP=3 -> 288 CTAs = one full wave. Fused deterministic final reduction.

#define W 512
#define H 512
#define NIMG 96            // 32 batch * 3 channels
#define NSTRIP 3
#define ROWS_OUT 169       // 3*169 = 507 >= 506 interior rows
#define NBLK (NIMG * NSTRIP)
#define NT 256

__device__ float g_part[NBLK];
__device__ unsigned int g_count;   // zero-init; reset by last block each launch

__device__ __forceinline__ float frcp(float x) {
    float r; asm("rcp.approx.f32 %0, %1;" : "=f"(r) : "f"(x)); return r;
}
__device__ __forceinline__ uint32_t smem_u32(const void* p) {
    return (uint32_t)__cvta_generic_to_shared(p);
}
#define CP16(dst, src) \
    asm volatile("cp.async.cg.shared.global [%0], [%1], 16;" :: "r"(dst), "l"(src) : "memory")
#define CP_COMMIT() asm volatile("cp.async.commit_group;" ::: "memory")
#define CP_WAIT1()  asm volatile("cp.async.wait_group 1;" ::: "memory")
#define CP_WAIT0()  asm volatile("cp.async.wait_group 0;" ::: "memory")

// Process smem row RI (runtime), ring slot J (compile-time), row-in-strip KK.
// Taps: 12 cols 4q-4..4q+7 from f0/f1/f2; parity h selects 8 (warp-uniform).
#define PROC_ROW(RI, J, KK)                                                   \
do {                                                                          \
    const float4 f0a = sA[RI][u0];                                            \
    const float4 f1a = sA[RI][u];                                             \
    const float4 f2a = sA[RI][u2];                                            \
    const float4 f0b = sB[RI][u0];                                            \
    const float4 f1b = sB[RI][u];                                             \
    const float4 f2b = sB[RI][u2];                                            \
    const float a0 = h ? f0a.w : f0a.y;                                       \
    const float a1 = h ? f1a.x : f0a.z;                                       \
    const float a2 = h ? f1a.y : f0a.w;                                       \
    const float a3 = h ? f1a.z : f1a.x;                                       \
    const float a4 = h ? f1a.w : f1a.y;                                       \
    const float a5 = h ? f2a.x : f1a.z;                                       \
    const float a6 = h ? f2a.y : f1a.w;                                       \
    const float a7 = h ? f2a.z : f2a.x;                                       \
    const float b0 = h ? f0b.w : f0b.y;                                       \
    const float b1 = h ? f1b.x : f0b.z;                                       \
    const float b2 = h ? f1b.y : f0b.w;                                       \
    const float b3 = h ? f1b.z : f1b.x;                                       \
    const float b4 = h ? f1b.w : f1b.y;                                       \
    const float b5 = h ? f2b.x : f1b.z;                                       \
    const float b6 = h ? f2b.y : f1b.w;                                       \
    const float b7 = h ? f2b.z : f2b.x;                                       \
    const float LA0 = ((a0 + a1) + (a2 + a3)) + ((a4 + a5) + a6);             \
    const float LB0 = ((b0 + b1) + (b2 + b3)) + ((b4 + b5) + b6);             \
    const float LA1 = (LA0 - a0) + a7;                                        \
    const float LB1 = (LB0 - b0) + b7;                                        \
    float Q0 = a0 * a0;                                                       \
    Q0 = fmaf(b0, b0, Q0);                                                    \
    Q0 = fmaf(a1, a1, Q0); Q0 = fmaf(b1, b1, Q0);                             \
    Q0 = fmaf(a2, a2, Q0); Q0 = fmaf(b2, b2, Q0);                             \
    Q0 = fmaf(a3, a3, Q0); Q0 = fmaf(b3, b3, Q0);                             \
    Q0 = fmaf(a4, a4, Q0); Q0 = fmaf(b4, b4, Q0);                             \
    Q0 = fmaf(a5, a5, Q0); Q0 = fmaf(b5, b5, Q0);                             \
    Q0 = fmaf(a6, a6, Q0); Q0 = fmaf(b6, b6, Q0);                             \
    float Q1 = fmaf(a7, a7, Q0);                                              \
    Q1 = fmaf(a0, -a0, Q1);                                                   \
    Q1 = fmaf(b7, b7, Q1);                                                    \
    Q1 = fmaf(b0, -b0, Q1);                                                   \
    const float pr0 = a0 * b0;                                                \
    float P0 = pr0;                                                           \
    P0 = fmaf(a1, b1, P0); P0 = fmaf(a2, b2, P0); P0 = fmaf(a3, b3, P0);      \
    P0 = fmaf(a4, b4, P0); P0 = fmaf(a5, b5, P0); P0 = fmaf(a6, b6, P0);      \
    const float P1 = fmaf(a7, b7, P0 - pr0);                                  \
    vA0 += LA0 - rA0[J];  rA0[J] = LA0;                                       \
    vB0 += LB0 - rB0[J];  rB0[J] = LB0;                                       \
    vQ0 += Q0  - rQ0[J];  rQ0[J] = Q0;                                        \
    vP0 += P0  - rP0[J];  rP0[J] = P0;                                        \
    vA1 += LA1 - rA1[J];  rA1[J] = LA1;                                       \
    vB1 += LB1 - rB1[J];  rB1[J] = LB1;                                       \
    vQ1 += Q1  - rQ1[J];  rQ1[J] = Q1;                                        \
    vP1 += P1  - rP1[J];  rP1[J] = P1;                                        \
    {                                                                         \
        const bool yok = ((KK) >= 6) && ((KK) <= klim);                       \
        const float ux0 = vA0 * INV49, uy0 = vB0 * INV49;                     \
        const float tt0 = ux0 * uy0;                                          \
        const float A1v0 = fmaf(tt0, 2.0f, C1);                               \
        float A2v0 = fmaf(vP0, TWO_CN_49, C2);                                \
        A2v0 = fmaf(tt0, -TWO_CN, A2v0);                                      \
        const float q20 = fmaf(uy0, uy0, ux0 * ux0);                          \
        const float B1v0 = q20 + C1;                                          \
        float B2v0 = fmaf(vQ0, CN_49, C2);                                    \
        B2v0 = fmaf(q20, -CN, B2v0);                                          \
        const float N0 = A1v0 * A2v0;                                         \
        const float D0 = B1v0 * B2v0;                                         \
        const float ux1 = vA1 * INV49, uy1 = vB1 * INV49;                     \
        const float tt1 = ux1 * uy1;                                          \
        const float A1v1 = fmaf(tt1, 2.0f, C1);                               \
        float A2v1 = fmaf(vP1, TWO_CN_49, C2);                                \
        A2v1 = fmaf(tt1, -TWO_CN, A2v1);                                      \
        const float q21 = fmaf(uy1, uy1, ux1 * ux1);                          \
        const float B1v1 = q21 + C1;                                          \
        float B2v1 = fmaf(vQ1, CN_49, C2);                                    \
        B2v1 = fmaf(q21, -CN, B2v1);                                          \
        const float N1 = A1v1 * A2v1;                                         \
        const float D1 = B1v1 * B2v1;                                         \
        const float R = frcp(D0 * D1);                                        \
        const float S0 = N0 * D1 * R;                                         \
        const float S1 = N1 * D0 * R;                                         \
        acc += (ok0 && yok) ? S0 : 0.0f;                                      \
        acc += (ok1 && yok) ? S1 : 0.0f;                                      \
    }                                                                         \
} while (0)

__global__ void __launch_bounds__(NT, 2) ssim_main(const float* __restrict__ A,
                                                   const float* __restrict__ B,
                                                   float* __restrict__ out) {
    // NP=49, CONV_NORM=49/48, C1=1e-4, C2=9e-4 (folded)
    const float C1        = 1e-4f;
    const float C2        = 9e-4f;
    const float INV49     = 1.0f / 49.0f;
    const float CN        = 49.0f / 48.0f;
    const float TWO_CN    = 49.0f / 24.0f;
    const float CN_49     = 1.0f / 48.0f;    // CN/49
    const float TWO_CN_49 = 1.0f / 24.0f;    // 2*CN/49

    const int t     = threadIdx.x;
    const int h     = t >> 7;          // warp-uniform: 0 = even pairs + stage A
    const int q     = t & 127;
    const int blk   = blockIdx.x;
    const int img   = blk % NIMG;
    const int strip = blk / NIMG;

    const size_t base = (size_t)img * (W * H);

    // 3-pair (6-row) smem rings, one per image
    __shared__ float4 sA[6][128];
    __shared__ float4 sB[6][128];

    // Staging: this thread copies 16B chunk q of its plane's rows
    const float* __restrict__ gsrc = (h ? B : A) + base + (size_t)q * 4;
    const uint32_t sbase = smem_u32(h ? (const void*)sB : (const void*)sA)
                         + (uint32_t)q * 16u;

    // Reader tap indices: cols 4q-4..4q+7 via float4 u-1,u,u+1 (clamped;
    // clamp junk feeds only masked columns or cancels in the col1 slide)
    const int u  = q;
    const int u0 = max(u - 1, 0);
    const int u2 = min(u + 1, 127);

    const int  c0  = 4 * q + 2 * h;                // even column of this pair
    const bool ok0 = (c0 >= 3) && (c0 <= 508);
    const bool ok1 = (c0 + 1 >= 3) && (c0 + 1 <= 508);

    const int rstart = strip * ROWS_OUT;           // 0 / 169 / 338
    const int klim   = (strip == 2) ? 173 : 174;   // 169+169+168 = 506 rows

    // Vertical sliding state (per column): A, B, Q, P
    float vA0 = 0.f, vB0 = 0.f, vQ0 = 0.f, vP0 = 0.f;
    float vA1 = 0.f, vB1 = 0.f, vQ1 = 0.f, vP1 = 0.f;
    float rA0[7] = {0,0,0,0,0,0,0}, rB0[7] = {0,0,0,0,0,0,0};
    float rQ0[7] = {0,0,0,0,0,0,0}, rP0[7] = {0,0,0,0,0,0,0};
    float rA1[7] = {0,0,0,0,0,0,0}, rB1[7] = {0,0,0,0,0,0,0};
    float rQ1[7] = {0,0,0,0,0,0,0}, rP1[7] = {0,0,0,0,0,0,0};
    float acc = 0.0f;

    // Prologue: issue pairs 0 (slot 0) and 1 (slot 1)
    {
        const int r0 = rstart;
        CP16(sbase + 0u * 2048u, gsrc + (size_t)(r0 + 0) * W);
        CP16(sbase + 1u * 2048u, gsrc + (size_t)(r0 + 1) * W);
        CP_COMMIT();
        CP16(sbase + 2u * 2048u, gsrc + (size_t)(r0 + 2) * W);
        CP16(sbase + 3u * 2048u, gsrc + (size_t)(r0 + 3) * W);
        CP_COMMIT();
    }

    int slot = 0;   // ring slot (0..2) of the pair being processed

    // 91 pairs = 182 rows (13 x 7 pairs); ring slot row%7 compile-time.
    // Rows 175..181 are clamped re-reads; emits beyond klim are masked.
    #pragma unroll 1
    for (int it = 0; it < 13; it++) {
        const int kb = it * 14;
        #pragma unroll
        for (int m = 0; m < 7; m++) {
            const int i = it * 7 + m;        // current pair index

            CP_WAIT1();                      // own copies of pair i complete
            __syncthreads();                 // all threads' copies complete;
                                             // also: all reads of pair i-1 done

            // Issue pair i+2 into slot (slot+2)%3 (= pair i-1's slot, now free)
            {
                const int s2 = (slot + 2 >= 3) ? slot - 1 : slot + 2;
                const int rr0 = min(rstart + 2 * (i + 2),     H - 1);
                const int rr1 = min(rstart + 2 * (i + 2) + 1, H - 1);
                const uint32_t d = sbase + (uint32_t)s2 * 4096u;
                CP16(d,          gsrc + (size_t)rr0 * W);
                CP16(d + 2048u,  gsrc + (size_t)rr1 * W);
                CP_COMMIT();
            }

            const int k0 = kb + 2 * m;
            const int ri = slot * 2;
            PROC_ROW(ri,     (2 * m) % 7,     k0);
            PROC_ROW(ri + 1, (2 * m + 1) % 7, k0 + 1);

            slot = (slot + 1 >= 3) ? 0 : slot + 1;
        }
    }
    CP_WAIT0();   // drain trailing copies before smem reuse / exit

    // Deterministic block reduction
    #pragma unroll
    for (int o = 16; o > 0; o >>= 1)
        acc += __shfl_xor_sync(0xFFFFFFFFu, acc, o);

    __shared__ float wsum[8];
    __shared__ bool  is_last;
    if ((t & 31) == 0) wsum[t >> 5] = acc;
    __syncthreads();
    if (t == 0) {
        float v = wsum[0] + wsum[1] + wsum[2] + wsum[3]
                + wsum[4] + wsum[5] + wsum[6] + wsum[7];
        g_part[blk] = v;
        __threadfence();
        unsigned int prev = atomicAdd(&g_count, 1u);
        is_last = (prev == NBLK - 1);
    }
    __syncthreads();

    // Last finished CTA: fixed-order double-precision final sum (deterministic)
    if (is_last) {
        double s = 0.0;
        for (int i = t; i < NBLK; i += NT) s += (double)__ldcg(&g_part[i]);
        __shared__ double sd[NT];
        sd[t] = s;
        __syncthreads();
        #pragma unroll
        for (int st = NT / 2; st > 0; st >>= 1) {
            if (t < st) sd[t] += sd[t + st];
            __syncthreads();
        }
        if (t == 0) {
            out[0] = (float)(sd[0] * (1.0 / ((double)NIMG * 506.0 * 506.0)));
            g_count = 0;   // reset for next graph replay
        }
    }
}

extern "C" void kernel_launch(void* const* d_in, const int* in_sizes, int n_in,
                              void* d_out, int out_size) {
    const float* img1 = (const float*)d_in[0];
    const float* img2 = (const float*)d_in[1];
    float* out = (float*)d_out;
    (void)in_sizes; (void)n_in; (void)out_size;

    ssim_main<<<NBLK, NT>>>(img1, img2, out);
}